// round 15
// baseline (speedup 1.0000x reference)
#include <cuda_runtime.h>
#include <cstdint>

#define BATCH 1024
#define NV 6890
#define KJ 24
#define NBETA 10
#define NPOSE 207
#define NPP 208          // 207 pose rows + 1 zero pad (=13*16)
#define NC 20670         // NV*3
#define NCHUNKS 13
#define NSEG 36          // k1a vertex tiles
#define NVSEG 192        // 36*192 = 6912 >= 6890
#define NOUT 792         // 24*33 reduction outputs

// ---- scratch (device globals; no allocations allowed) ----
__device__ float g_part[NSEG * NOUT];
__device__ float g_pfT[NPP * BATCH];      // pose feature transposed [p][b], row 207 = 0
__device__ float g_A[BATCH * KJ * 12];    // per batch/joint 3x4 [R|t]

// ---- output layout (concatenated tuple, float32) ----
#define OUT_JT   (BATCH * NV * 3)
#define OUT_J    (OUT_JT + BATCH * KJ * 3)
#define OUT_ROT  (OUT_J + BATCH * KJ * 3)

// ---- packed f32x2 helpers ----
typedef unsigned long long u64;
__device__ __forceinline__ u64 pk2(float lo, float hi) {
    u64 r; asm("mov.b64 %0, {%1, %2};" : "=l"(r) : "f"(lo), "f"(hi)); return r;
}
__device__ __forceinline__ void upk2(u64 v, float& lo, float& hi) {
    asm("mov.b64 {%0, %1}, %2;" : "=f"(lo), "=f"(hi) : "l"(v));
}
__device__ __forceinline__ u64 ff2(u64 a, u64 b, u64 c) {
    u64 d; asm("fma.rn.f32x2 %0, %1, %2, %3;" : "=l"(d) : "l"(a), "l"(b), "l"(c));
    return d;
}

// ---- cp.async helpers ----
__device__ __forceinline__ void cpa16(uint32_t dst, const void* src, int sb) {
    asm volatile("cp.async.cg.shared.global [%0], [%1], 16, %2;"
                 :: "r"(dst), "l"(src), "r"(sb));
}
__device__ __forceinline__ void cpa8(uint32_t dst, const void* src, int sb) {
    asm volatile("cp.async.ca.shared.global [%0], [%1], 8, %2;"
                 :: "r"(dst), "l"(src), "r"(sb));
}
__device__ __forceinline__ void cpcommit() {
    asm volatile("cp.async.commit_group;");
}

#define MMA_TF32(d, a, b) \
    asm volatile("mma.sync.aligned.m16n8k8.row.col.f32.tf32.tf32.f32 " \
        "{%0,%1,%2,%3}, {%4,%5,%6,%7}, {%8,%9}, {%0,%1,%2,%3};" \
        : "+f"(d[0]), "+f"(d[1]), "+f"(d[2]), "+f"(d[3]) \
        : "r"(a[0]), "r"(a[1]), "r"(a[2]), "r"(a[3]), "r"(b[0]), "r"(b[1]))

// ============================================================================
// Kernel 1a: C[24x33] partials via smem-tiled dot products.
// 36 blocks x 192-vertex tiles; coalesced loads, no shuffles.
// smem: sd tile padded stride 31 (conflict-free), vt tile, 24 Jreg rows.
// ============================================================================
__global__ __launch_bounds__(256) void k1a_jreduce(
    const float* __restrict__ Jreg,
    const float* __restrict__ vt,
    const float* __restrict__ sd)
{
    __shared__ float sSD[NVSEG * 31];     // 5952
    __shared__ float sVT[NVSEG * 3];      // 576
    __shared__ float sJ[KJ * NVSEG];      // 4608
    int tid = threadIdx.x;
    int seg = blockIdx.x;
    int v0 = seg * NVSEG;

    // sd tile: linear/coalesced read of 192*30 floats, pad to stride 31
    for (int i = tid; i < NVSEG * 30; i += 256) {
        size_t gi = (size_t)v0 * 30 + i;
        float val = (gi < (size_t)NV * 30) ? sd[gi] : 0.f;
        sSD[(i / 30) * 31 + (i % 30)] = val;
    }
    // vt tile: 576 floats linear
    for (int i = tid; i < NVSEG * 3; i += 256) {
        size_t gi = (size_t)v0 * 3 + i;
        sVT[i] = (gi < (size_t)NV * 3) ? vt[gi] : 0.f;
    }
    // Jreg rows: 24 x 192, coalesced per row
#pragma unroll
    for (int k = 0; k < KJ; k++) {
        for (int i = tid; i < NVSEG; i += 256) {
            int v = v0 + i;
            sJ[k * NVSEG + i] = (v < NV) ? Jreg[(size_t)k * NV + v] : 0.f;
        }
    }
    __syncthreads();

    // each thread: ~3 outputs, 192-length smem dot each
    for (int o = tid; o < NOUT; o += 256) {
        int k = o / 33, e = o % 33;
        const float* jr = sJ + k * NVSEG;
        float s = 0.f;
        if (e < 3) {
#pragma unroll 4
            for (int v = 0; v < NVSEG; v++)
                s = fmaf(jr[v], sVT[v * 3 + e], s);
        } else {
            int eo = e - 3;
#pragma unroll 4
            for (int v = 0; v < NVSEG; v++)
                s = fmaf(jr[v], sSD[v * 31 + eo], s);
        }
        g_part[seg * NOUT + o] = s;
    }
}

// ============================================================================
// Kernel 2: 8 batches/block, one warp per batch. Fuses the segment combine
// (792 sums of 36 from g_part into smem). Rodrigues, pose feature, joints_t,
// kinematic chain, A matrices (plain [b][k][12] layout).
// ============================================================================
__global__ __launch_bounds__(256) void k2_batch(
    const float* __restrict__ body_pose,
    const float* __restrict__ betas,
    const float* __restrict__ global_orient,
    const int* __restrict__ parents,
    float* __restrict__ out)
{
    int tidx = threadIdx.x;
    int w = tidx >> 5;
    int t = tidx & 31;
    int b = blockIdx.x * 8 + w;
    __shared__ float sJT0[KJ * 3];
    __shared__ float sJS[KJ * 30];
    __shared__ float Rm[8][KJ][9];
    __shared__ float jt[8][KJ][3];
    __shared__ float rel[8][KJ][3];
    __shared__ float ch[8][KJ][12];

    // ---- fused combine: sum 36 segment partials into smem ----
    for (int i = tidx; i < NOUT; i += 256) {
        int k = i / 33, e = i % 33;
        float s = 0.f;
#pragma unroll
        for (int seg = 0; seg < NSEG; seg++) s += g_part[seg * NOUT + i];
        if (e < 3) sJT0[k * 3 + e] = s;
        else       sJS[k * 30 + (e - 3)] = s;
    }
    __syncthreads();

    if (t < KJ) {
        float ax, ay, az;
        if (t == 0) {
            ax = global_orient[b * 3 + 0];
            ay = global_orient[b * 3 + 1];
            az = global_orient[b * 3 + 2];
        } else {
            const float* p = body_pose + b * 69 + (t - 1) * 3;
            ax = p[0]; ay = p[1]; az = p[2];
        }
        float ex = ax + 1e-8f, ey = ay + 1e-8f, ez = az + 1e-8f;
        float angle = sqrtf(ex * ex + ey * ey + ez * ez);
        float inv = 1.0f / angle;
        float ux = ax * inv, uy = ay * inv, uz = az * inv;
        float s = sinf(angle), c = cosf(angle);
        float oc = 1.0f - c;
        float uu = ux * ux + uy * uy + uz * uz;
        float r0 = 1.0f + oc * (ux * ux - uu);
        float r1 = -s * uz + oc * (ux * uy);
        float r2 =  s * uy + oc * (ux * uz);
        float r3 =  s * uz + oc * (uy * ux);
        float r4 = 1.0f + oc * (uy * uy - uu);
        float r5 = -s * ux + oc * (uy * uz);
        float r6 = -s * uy + oc * (uz * ux);
        float r7 =  s * ux + oc * (uz * uy);
        float r8 = 1.0f + oc * (uz * uz - uu);
        Rm[w][t][0] = r0; Rm[w][t][1] = r1; Rm[w][t][2] = r2;
        Rm[w][t][3] = r3; Rm[w][t][4] = r4; Rm[w][t][5] = r5;
        Rm[w][t][6] = r6; Rm[w][t][7] = r7; Rm[w][t][8] = r8;

        float* ro = out + OUT_ROT + (size_t)b * 216 + t * 9;
        ro[0] = r0; ro[1] = r1; ro[2] = r2; ro[3] = r3; ro[4] = r4;
        ro[5] = r5; ro[6] = r6; ro[7] = r7; ro[8] = r8;

        if (t >= 1) {
            int p0 = (t - 1) * 9;
            g_pfT[(p0 + 0) * BATCH + b] = r0 - 1.0f;
            g_pfT[(p0 + 1) * BATCH + b] = r1;
            g_pfT[(p0 + 2) * BATCH + b] = r2;
            g_pfT[(p0 + 3) * BATCH + b] = r3;
            g_pfT[(p0 + 4) * BATCH + b] = r4 - 1.0f;
            g_pfT[(p0 + 5) * BATCH + b] = r5;
            g_pfT[(p0 + 6) * BATCH + b] = r6;
            g_pfT[(p0 + 7) * BATCH + b] = r7;
            g_pfT[(p0 + 8) * BATCH + b] = r8 - 1.0f;
        } else {
            g_pfT[207 * BATCH + b] = 0.0f;   // pad row
        }

#pragma unroll
        for (int cc = 0; cc < 3; cc++) {
            float s2 = sJT0[t * 3 + cc];
#pragma unroll
            for (int l = 0; l < NBETA; l++)
                s2 = fmaf(sJS[t * 30 + cc * 10 + l], betas[b * 10 + l], s2);
            jt[w][t][cc] = s2;
            out[OUT_JT + (size_t)b * 72 + t * 3 + cc] = s2;
        }
    }
    __syncwarp();
    if (t < KJ) {
        if (t == 0) {
            rel[w][0][0] = jt[w][0][0]; rel[w][0][1] = jt[w][0][1]; rel[w][0][2] = jt[w][0][2];
        } else {
            int p = parents[t];
            rel[w][t][0] = jt[w][t][0] - jt[w][p][0];
            rel[w][t][1] = jt[w][t][1] - jt[w][p][1];
            rel[w][t][2] = jt[w][t][2] - jt[w][p][2];
        }
    }
    __syncwarp();
    if (t < 12) {
        int i = t >> 2, j = t & 3;
        ch[w][0][t] = (j < 3) ? Rm[w][0][i * 3 + j] : rel[w][0][i];
    }
    __syncwarp();
    for (int k = 1; k < KJ; k++) {
        int p = parents[k];
        if (t < 12) {
            int i = t >> 2, j = t & 3;
            float v;
            if (j < 3) {
                v = ch[w][p][i * 4 + 0] * Rm[w][k][0 * 3 + j]
                  + ch[w][p][i * 4 + 1] * Rm[w][k][1 * 3 + j]
                  + ch[w][p][i * 4 + 2] * Rm[w][k][2 * 3 + j];
            } else {
                v = ch[w][p][i * 4 + 0] * rel[w][k][0]
                  + ch[w][p][i * 4 + 1] * rel[w][k][1]
                  + ch[w][p][i * 4 + 2] * rel[w][k][2]
                  + ch[w][p][i * 4 + 3];
            }
            ch[w][k][t] = v;
        }
        __syncwarp();
    }
    if (t < KJ) {
        out[OUT_J + (size_t)b * 72 + t * 3 + 0] = ch[w][t][3];
        out[OUT_J + (size_t)b * 72 + t * 3 + 1] = ch[w][t][7];
        out[OUT_J + (size_t)b * 72 + t * 3 + 2] = ch[w][t][11];
        float* Ao = g_A + ((size_t)b * KJ + t) * 12;
#pragma unroll
        for (int i = 0; i < 3; i++) {
            float tr = ch[w][t][i * 4 + 3]
                     - (ch[w][t][i * 4 + 0] * jt[w][t][0]
                      + ch[w][t][i * 4 + 1] * jt[w][t][1]
                      + ch[w][t][i * 4 + 2] * jt[w][t][2]);
            Ao[i * 4 + 0] = ch[w][t][i * 4 + 0];
            Ao[i * 4 + 1] = ch[w][t][i * 4 + 1];
            Ao[i * 4 + 2] = ch[w][t][i * 4 + 2];
            Ao[i * 4 + 3] = tr;
        }
    }
}

// ============================================================================
// Kernel 3 (R3's best-measured version, verbatim): tf32 mma.sync GEMM
// (v_pose-delta) + fp32 shape + FFMA2 LBS.
// Block: 192 coords x 64 batches, 256 threads (8 warps, 4m x 2n).
// Warp tile 48x32 -> 3x4 m16n8k8 frags, 48 fp32 accums/thread.
// grid = (16, 108). cp.async 3-stage pipeline.
// ============================================================================
#define SF_STAGE 4352                 // A 16x200=3200 + B 16x72=1152
#define CS_STRIDE 65                  // Csm 192x65 = 12480 (aliases stages)
#define S_W     13056                 // 24*64 = 1536
#define S_AMAT  (S_W + 1536)          // 64*288 = 18432
#define S_SD    (S_AMAT + 18432)      // 64*30 = 1920
#define S_VT    (S_SD + 1920)         // 192
#define S_BET   (S_VT + 192)          // 640
#define SMEM_FL (S_BET + 640)         // 35776
#define SMEM_BYTES (SMEM_FL * 4)

__device__ __forceinline__ void k3_load_stage(uint32_t smb,
                                              const float* __restrict__ posedirs,
                                              int n0, int kc, int st, int tid)
{
    // A tile: rows p = kc*16 .. +15, cols n0 .. n0+191, 8B ops
#pragma unroll
    for (int j = 0; j < 6; j++) {
        int i = tid + j * 256;            // < 1536
        int row = i / 96, c2 = i % 96;
        int p = kc * 16 + row;
        int col = n0 + c2 * 2;
        int sb = 0;
        if (p < NPOSE) {
            int rem = NC - col;
            sb = (rem >= 2) ? 8 : 0;
        }
        const float* src = posedirs + (size_t)min(p, NPOSE - 1) * NC
                                    + (sb ? col : 0);
        cpa8(smb + (uint32_t)(st * SF_STAGE + row * 200 + c2 * 2) * 4, src, sb);
    }
    // B tile: pfT rows, 16B ops (always in-bounds; row 207 is zero pad)
    {
        int row = tid / 16, c4 = tid % 16;
        int p = kc * 16 + row;
        int bBase = blockIdx.x * 64;
        cpa16(smb + (uint32_t)(st * SF_STAGE + 3200 + row * 72 + c4 * 4) * 4,
              g_pfT + (size_t)p * BATCH + bBase + c4 * 4, 16);
    }
}

__global__ __launch_bounds__(256, 1) void k3_lbs(
    const float* __restrict__ posedirs,
    const float* __restrict__ lbs_w,
    const float* __restrict__ shapedirs,
    const float* __restrict__ v_template,
    const float* __restrict__ betas,
    float* __restrict__ out)
{
    extern __shared__ float sm[];
    uint32_t smb = (uint32_t)__cvta_generic_to_shared(sm);
    int tid = threadIdx.x;
    int lane = tid & 31, warp = tid >> 5;
    int bBase = blockIdx.x * 64;
    int n0 = blockIdx.y * 192;
    int v0 = n0 / 3;
    int mW = (warp & 3) * 48;
    int nW = (warp >> 2) * 32;

    // ---- epilogue tables via cp.async (group 0) ----
    {
        // A matrices: 64*288 floats contiguous = 4608 x16B
#pragma unroll
        for (int j = 0; j < 18; j++) {
            int i = tid + j * 256;
            cpa16(smb + (uint32_t)(S_AMAT + i * 4) * 4,
                  g_A + (size_t)bBase * 288 + i * 4, 16);
        }
        // shapedirs rows [v0, v0+64): 1920 floats, clamp at NV
        int validf = (NV - v0) * 30; if (validf > 1920) validf = 1920;
#pragma unroll
        for (int j = 0; j < 2; j++) {
            int i = tid + j * 256;
            if (i < 480) {
                int fo = i * 4;
                int rem = validf - fo;
                int sb = rem >= 4 ? 16 : (rem > 0 ? rem * 4 : 0);
                cpa16(smb + (uint32_t)(S_SD + fo) * 4,
                      shapedirs + (size_t)v0 * 30 + (sb ? fo : 0), sb);
            }
        }
        // v_template: 192 floats
        if (tid < 48) {
            int fo = tid * 4;
            int validv = (NV - v0) * 3; if (validv > 192) validv = 192;
            int rem = validv - fo;
            int sb = rem >= 4 ? 16 : (rem > 0 ? rem * 4 : 0);
            cpa16(smb + (uint32_t)(S_VT + fo) * 4,
                  v_template + (size_t)v0 * 3 + (sb ? fo : 0), sb);
        }
        // betas: 640 floats (always in-bounds)
        if (tid < 160) {
            cpa16(smb + (uint32_t)(S_BET + tid * 4) * 4,
                  betas + (size_t)bBase * 10 + tid * 4, 16);
        }
    }
    cpcommit();

    // ---- prefetch GEMM chunks 0, 1 ----
    k3_load_stage(smb, posedirs, n0, 0, 0, tid); cpcommit();
    k3_load_stage(smb, posedirs, n0, 1, 1, tid); cpcommit();

    // ---- weights (transposed [k][64]) via plain loads, overlap with cp.async
#pragma unroll
    for (int j = 0; j < 6; j++) {
        int i = tid + j * 256;
        int k = i >> 6, vl = i & 63;
        int vg = v0 + vl;
        sm[S_W + k * 64 + vl] = (vg < NV) ? lbs_w[vg * KJ + k] : 0.f;
    }

    float acc[3][4][4];
#pragma unroll
    for (int it = 0; it < 3; it++)
#pragma unroll
        for (int jt = 0; jt < 4; jt++)
#pragma unroll
            for (int e = 0; e < 4; e++) acc[it][jt][e] = 0.f;

    // ---- main k-loop ----
    int st = 0;
    for (int kc = 0; kc < NCHUNKS; kc++) {
        if (kc + 2 < NCHUNKS) {
            int ns = st + 2; if (ns >= 3) ns -= 3;
            k3_load_stage(smb, posedirs, n0, kc + 2, ns, tid);
        }
        cpcommit();
        asm volatile("cp.async.wait_group 2;");
        __syncthreads();

        const float* As = sm + st * SF_STAGE;
        const float* Bs = As + 3200;
#pragma unroll
        for (int kk = 0; kk < 2; kk++) {
            int k0 = kk * 8;
            uint32_t a[3][4], b[4][2];
            int ar0 = (k0 + (lane & 3)) * 200 + mW + (lane >> 2);
            int ar1 = ar0 + 4 * 200;
#pragma unroll
            for (int it = 0; it < 3; it++) {
                a[it][0] = __float_as_uint(As[ar0 + it * 16]);
                a[it][1] = __float_as_uint(As[ar0 + it * 16 + 8]);
                a[it][2] = __float_as_uint(As[ar1 + it * 16]);
                a[it][3] = __float_as_uint(As[ar1 + it * 16 + 8]);
            }
            int br0 = (k0 + (lane & 3)) * 72 + nW + (lane >> 2);
            int br1 = br0 + 4 * 72;
#pragma unroll
            for (int jt = 0; jt < 4; jt++) {
                b[jt][0] = __float_as_uint(Bs[br0 + jt * 8]);
                b[jt][1] = __float_as_uint(Bs[br1 + jt * 8]);
            }
#pragma unroll
            for (int it = 0; it < 3; it++)
#pragma unroll
                for (int jt = 0; jt < 4; jt++)
                    MMA_TF32(acc[it][jt], a[it], b[jt]);
        }
        __syncthreads();   // stage st free for reuse by prefetch
        st = st + 1; if (st >= 3) st = 0;
    }

    // ---- dump accumulators to Csm (stage region is dead) ----
    {
        float* Cs = sm;
#pragma unroll
        for (int it = 0; it < 3; it++)
#pragma unroll
            for (int jt = 0; jt < 4; jt++) {
                int m = mW + it * 16 + (lane >> 2);
                int n = nW + jt * 8 + 2 * (lane & 3);
                Cs[m * CS_STRIDE + n]           = acc[it][jt][0];
                Cs[m * CS_STRIDE + n + 1]       = acc[it][jt][1];
                Cs[(m + 8) * CS_STRIDE + n]     = acc[it][jt][2];
                Cs[(m + 8) * CS_STRIDE + n + 1] = acc[it][jt][3];
            }
    }
    asm volatile("cp.async.wait_group 0;");   // epilogue tables ready
    __syncthreads();

    // ---- epilogue: v_posed = Csm + template + shape (fp32), then LBS ----
    int tn = tid & 15;
    int tb = tid >> 4;
    const float* Cs   = sm;
    const float* w_s  = sm + S_W;
    const float* a_s  = sm + S_AMAT;
    const float* sd_s = sm + S_SD;
    const float* vt_s = sm + S_VT;
    const float* bt_s = sm + S_BET;

    float vpf[4][12];
    {
        float bet[4][10];
#pragma unroll
        for (int bi = 0; bi < 4; bi++)
#pragma unroll
            for (int l = 0; l < NBETA; l++)
                bet[bi][l] = bt_s[(tb * 4 + bi) * 10 + l];
#pragma unroll
        for (int vi = 0; vi < 4; vi++) {
            int vl = tn * 4 + vi;
#pragma unroll
            for (int c = 0; c < 3; c++) {
                float base = vt_s[vl * 3 + c];
                float sdv[10];
#pragma unroll
                for (int l = 0; l < NBETA; l++) sdv[l] = sd_s[vl * 30 + c * 10 + l];
                int mrow = vl * 3 + c;
#pragma unroll
                for (int bi = 0; bi < 4; bi++) {
                    float s = base;
#pragma unroll
                    for (int l = 0; l < NBETA; l++) s = fmaf(bet[bi][l], sdv[l], s);
                    vpf[bi][vi * 3 + c] = Cs[mrow * CS_STRIDE + tb * 4 + bi] + s;
                }
            }
        }
    }

    // pack vertex pairs for FFMA2 LBS
    u64 xs2[4][2], ys2[4][2], zs2[4][2];
#pragma unroll
    for (int bi = 0; bi < 4; bi++)
#pragma unroll
        for (int h = 0; h < 2; h++) {
            xs2[bi][h] = pk2(vpf[bi][(2 * h) * 3 + 0], vpf[bi][(2 * h + 1) * 3 + 0]);
            ys2[bi][h] = pk2(vpf[bi][(2 * h) * 3 + 1], vpf[bi][(2 * h + 1) * 3 + 1]);
            zs2[bi][h] = pk2(vpf[bi][(2 * h) * 3 + 2], vpf[bi][(2 * h + 1) * 3 + 2]);
        }

    u64 o2[4][3][2];
#pragma unroll
    for (int bi = 0; bi < 4; bi++)
#pragma unroll
        for (int c = 0; c < 3; c++) { o2[bi][c][0] = 0ULL; o2[bi][c][1] = 0ULL; }

    for (int k = 0; k < KJ; k++) {
        float4 w4 = *(const float4*)&w_s[k * 64 + tn * 4];
        u64 w2[2] = {pk2(w4.x, w4.y), pk2(w4.z, w4.w)};
#pragma unroll
        for (int bi = 0; bi < 4; bi++) {
            const float* Ab = a_s + (tb * 4 + bi) * 288 + k * 12;
            float4 r0 = *(const float4*)&Ab[0];
            float4 r1 = *(const float4*)&Ab[4];
            float4 r2 = *(const float4*)&Ab[8];
            u64 r0x = pk2(r0.x, r0.x), r0y = pk2(r0.y, r0.y),
                r0z = pk2(r0.z, r0.z), r0w = pk2(r0.w, r0.w);
            u64 r1x = pk2(r1.x, r1.x), r1y = pk2(r1.y, r1.y),
                r1z = pk2(r1.z, r1.z), r1w = pk2(r1.w, r1.w);
            u64 r2x = pk2(r2.x, r2.x), r2y = pk2(r2.y, r2.y),
                r2z = pk2(r2.z, r2.z), r2w = pk2(r2.w, r2.w);
#pragma unroll
            for (int h = 0; h < 2; h++) {
                u64 tx = ff2(r0x, xs2[bi][h], ff2(r0y, ys2[bi][h], ff2(r0z, zs2[bi][h], r0w)));
                u64 ty = ff2(r1x, xs2[bi][h], ff2(r1y, ys2[bi][h], ff2(r1z, zs2[bi][h], r1w)));
                u64 tz = ff2(r2x, xs2[bi][h], ff2(r2y, ys2[bi][h], ff2(r2z, zs2[bi][h], r2w)));
                o2[bi][0][h] = ff2(w2[h], tx, o2[bi][0][h]);
                o2[bi][1][h] = ff2(w2[h], ty, o2[bi][1][h]);
                o2[bi][2][h] = ff2(w2[h], tz, o2[bi][2][h]);
            }
        }
    }

    // ---- store vertices (float2: NC even -> always aligned) ----
#pragma unroll
    for (int bi = 0; bi < 4; bi++) {
        float ov[12];
#pragma unroll
        for (int c = 0; c < 3; c++)
#pragma unroll
            for (int h = 0; h < 2; h++)
                upk2(o2[bi][c][h], ov[(2 * h) * 3 + c], ov[(2 * h + 1) * 3 + c]);
        int gb = bBase + tb * 4 + bi;
        size_t base = (size_t)gb * NC + n0 + tn * 12;
        int n = n0 + tn * 12;
        if (n + 12 <= NC) {
#pragma unroll
            for (int j = 0; j < 6; j++)
                *(float2*)&out[base + 2 * j] = make_float2(ov[2 * j], ov[2 * j + 1]);
        } else {
#pragma unroll
            for (int cj = 0; cj < 12; cj++)
                if (n + cj < NC) out[base + cj] = ov[cj];
        }
    }
}

// ============================================================================
extern "C" void kernel_launch(void* const* d_in, const int* in_sizes, int n_in,
                              void* d_out, int out_size)
{
    const float* body_pose     = (const float*)d_in[0];
    const float* betas         = (const float*)d_in[1];
    const float* global_orient = (const float*)d_in[2];
    const float* v_template    = (const float*)d_in[3];
    const float* shapedirs     = (const float*)d_in[4];
    const float* posedirs      = (const float*)d_in[5];
    const float* J_regressor   = (const float*)d_in[6];
    const float* lbs_weights   = (const float*)d_in[7];
    const int*   parents       = (const int*)d_in[8];
    float* out = (float*)d_out;

    static bool s_attr = false;
    if (!s_attr) {
        cudaFuncSetAttribute(k3_lbs, cudaFuncAttributeMaxDynamicSharedMemorySize,
                             SMEM_BYTES);
        s_attr = true;
    }

    k1a_jreduce<<<NSEG, 256>>>(J_regressor, v_template, shapedirs);
    k2_batch<<<BATCH / 8, 256>>>(body_pose, betas, global_orient, parents, out);
    k3_lbs<<<dim3(16, 108), 256, SMEM_BYTES>>>(posedirs, lbs_weights, shapedirs,
                                               v_template, betas, out);
}

// round 16
// speedup vs baseline: 1.0557x; 1.0557x over previous
#include <cuda_runtime.h>
#include <cstdint>

#define BATCH 1024
#define NV 6890
#define KJ 24
#define NBETA 10
#define NPOSE 207
#define NPP 208          // 207 pose rows + 1 zero pad (=13*16)
#define NC 20670         // NV*3
#define NCHUNKS 13
#define NSEG 8           // k1a segments per joint (R13-proven)
#define NVSEG 864

// ---- scratch (device globals; no allocations allowed) ----
__device__ float g_part[NSEG * KJ * 33];
__device__ float g_pfT[NPP * BATCH];      // pose feature transposed [p][b], row 207 = 0
__device__ float g_A[BATCH * KJ * 12];    // per batch/joint 3x4 [R|t]

// ---- output layout (concatenated tuple, float32) ----
#define OUT_JT   (BATCH * NV * 3)
#define OUT_J    (OUT_JT + BATCH * KJ * 3)
#define OUT_ROT  (OUT_J + BATCH * KJ * 3)

// ---- packed f32x2 helpers ----
typedef unsigned long long u64;
__device__ __forceinline__ u64 pk2(float lo, float hi) {
    u64 r; asm("mov.b64 %0, {%1, %2};" : "=l"(r) : "f"(lo), "f"(hi)); return r;
}
__device__ __forceinline__ void upk2(u64 v, float& lo, float& hi) {
    asm("mov.b64 {%0, %1}, %2;" : "=f"(lo), "=f"(hi) : "l"(v));
}
__device__ __forceinline__ u64 ff2(u64 a, u64 b, u64 c) {
    u64 d; asm("fma.rn.f32x2 %0, %1, %2, %3;" : "=l"(d) : "l"(a), "l"(b), "l"(c));
    return d;
}

// ---- cp.async helpers ----
__device__ __forceinline__ void cpa16(uint32_t dst, const void* src, int sb) {
    asm volatile("cp.async.cg.shared.global [%0], [%1], 16, %2;"
                 :: "r"(dst), "l"(src), "r"(sb));
}
__device__ __forceinline__ void cpa8(uint32_t dst, const void* src, int sb) {
    asm volatile("cp.async.ca.shared.global [%0], [%1], 8, %2;"
                 :: "r"(dst), "l"(src), "r"(sb));
}
__device__ __forceinline__ void cpcommit() {
    asm volatile("cp.async.commit_group;");
}

#define MMA_TF32(d, a, b) \
    asm volatile("mma.sync.aligned.m16n8k8.row.col.f32.tf32.tf32.f32 " \
        "{%0,%1,%2,%3}, {%4,%5,%6,%7}, {%8,%9}, {%0,%1,%2,%3};" \
        : "+f"(d[0]), "+f"(d[1]), "+f"(d[2]), "+f"(d[3]) \
        : "r"(a[0]), "r"(a[1]), "r"(a[2]), "r"(a[3]), "r"(b[0]), "r"(b[1]))

// ============================================================================
// Kernel 1a: partial reductions JT0/JS over V segments (R13-proven form)
// ============================================================================
__global__ void k1a_jreduce(const float* __restrict__ Jreg,
                            const float* __restrict__ vt,
                            const float* __restrict__ sd)
{
    int k = blockIdx.x;
    int seg = blockIdx.y;
    int tid = threadIdx.x;
    int v0 = seg * NVSEG;
    int v1 = min(NV, v0 + NVSEG);
    float acc[33];
#pragma unroll
    for (int e = 0; e < 33; e++) acc[e] = 0.f;

    for (int v = v0 + tid; v < v1; v += 256) {
        float j = Jreg[k * NV + v];
        const float* vp = vt + v * 3;
        acc[0] = fmaf(j, vp[0], acc[0]);
        acc[1] = fmaf(j, vp[1], acc[1]);
        acc[2] = fmaf(j, vp[2], acc[2]);
        const float* sp = sd + v * 30;
#pragma unroll
        for (int e = 0; e < 30; e++) acc[3 + e] = fmaf(j, sp[e], acc[3 + e]);
    }
#pragma unroll
    for (int e = 0; e < 33; e++) {
        for (int off = 16; off; off >>= 1)
            acc[e] += __shfl_down_sync(0xffffffffu, acc[e], off);
    }
    __shared__ float red[8][33];
    int lane = tid & 31, w = tid >> 5;
    if (lane == 0) {
#pragma unroll
        for (int e = 0; e < 33; e++) red[w][e] = acc[e];
    }
    __syncthreads();
    if (tid < 33) {
        float s = 0.f;
#pragma unroll
        for (int w2 = 0; w2 < 8; w2++) s += red[w2][tid];
        g_part[(k * NSEG + seg) * 33 + tid] = s;
    }
}

// ============================================================================
// Kernel 2: 8 batches/block, one warp per batch. Fuses the segment combine.
// Rodrigues, pose feature, joints_t, kinematic chain, A matrices.
// ============================================================================
__global__ __launch_bounds__(256) void k2_batch(
    const float* __restrict__ body_pose,
    const float* __restrict__ betas,
    const float* __restrict__ global_orient,
    const int* __restrict__ parents,
    float* __restrict__ out)
{
    int tidx = threadIdx.x;
    int w = tidx >> 5;
    int t = tidx & 31;
    int b = blockIdx.x * 8 + w;
    __shared__ float sJT0[KJ * 3];
    __shared__ float sJS[KJ * 30];
    __shared__ float Rm[8][KJ][9];
    __shared__ float jt[8][KJ][3];
    __shared__ float rel[8][KJ][3];
    __shared__ float ch[8][KJ][12];

    // ---- fused combine: sum 8 segment partials into smem ----
    for (int i = tidx; i < KJ * 33; i += 256) {
        int k = i / 33, e = i % 33;
        float s = 0.f;
#pragma unroll
        for (int seg = 0; seg < NSEG; seg++) s += g_part[(k * NSEG + seg) * 33 + e];
        if (e < 3) sJT0[k * 3 + e] = s;
        else       sJS[k * 30 + (e - 3)] = s;
    }
    __syncthreads();

    if (t < KJ) {
        float ax, ay, az;
        if (t == 0) {
            ax = global_orient[b * 3 + 0];
            ay = global_orient[b * 3 + 1];
            az = global_orient[b * 3 + 2];
        } else {
            const float* p = body_pose + b * 69 + (t - 1) * 3;
            ax = p[0]; ay = p[1]; az = p[2];
        }
        float ex = ax + 1e-8f, ey = ay + 1e-8f, ez = az + 1e-8f;
        float angle = sqrtf(ex * ex + ey * ey + ez * ez);
        float inv = 1.0f / angle;
        float ux = ax * inv, uy = ay * inv, uz = az * inv;
        float s = sinf(angle), c = cosf(angle);
        float oc = 1.0f - c;
        float uu = ux * ux + uy * uy + uz * uz;
        float r0 = 1.0f + oc * (ux * ux - uu);
        float r1 = -s * uz + oc * (ux * uy);
        float r2 =  s * uy + oc * (ux * uz);
        float r3 =  s * uz + oc * (uy * ux);
        float r4 = 1.0f + oc * (uy * uy - uu);
        float r5 = -s * ux + oc * (uy * uz);
        float r6 = -s * uy + oc * (uz * ux);
        float r7 =  s * ux + oc * (uz * uy);
        float r8 = 1.0f + oc * (uz * uz - uu);
        Rm[w][t][0] = r0; Rm[w][t][1] = r1; Rm[w][t][2] = r2;
        Rm[w][t][3] = r3; Rm[w][t][4] = r4; Rm[w][t][5] = r5;
        Rm[w][t][6] = r6; Rm[w][t][7] = r7; Rm[w][t][8] = r8;

        float* ro = out + OUT_ROT + (size_t)b * 216 + t * 9;
        ro[0] = r0; ro[1] = r1; ro[2] = r2; ro[3] = r3; ro[4] = r4;
        ro[5] = r5; ro[6] = r6; ro[7] = r7; ro[8] = r8;

        if (t >= 1) {
            int p0 = (t - 1) * 9;
            g_pfT[(p0 + 0) * BATCH + b] = r0 - 1.0f;
            g_pfT[(p0 + 1) * BATCH + b] = r1;
            g_pfT[(p0 + 2) * BATCH + b] = r2;
            g_pfT[(p0 + 3) * BATCH + b] = r3;
            g_pfT[(p0 + 4) * BATCH + b] = r4 - 1.0f;
            g_pfT[(p0 + 5) * BATCH + b] = r5;
            g_pfT[(p0 + 6) * BATCH + b] = r6;
            g_pfT[(p0 + 7) * BATCH + b] = r7;
            g_pfT[(p0 + 8) * BATCH + b] = r8 - 1.0f;
        } else {
            g_pfT[207 * BATCH + b] = 0.0f;   // pad row
        }

#pragma unroll
        for (int cc = 0; cc < 3; cc++) {
            float s2 = sJT0[t * 3 + cc];
#pragma unroll
            for (int l = 0; l < NBETA; l++)
                s2 = fmaf(sJS[t * 30 + cc * 10 + l], betas[b * 10 + l], s2);
            jt[w][t][cc] = s2;
            out[OUT_JT + (size_t)b * 72 + t * 3 + cc] = s2;
        }
    }
    __syncwarp();
    if (t < KJ) {
        if (t == 0) {
            rel[w][0][0] = jt[w][0][0]; rel[w][0][1] = jt[w][0][1]; rel[w][0][2] = jt[w][0][2];
        } else {
            int p = parents[t];
            rel[w][t][0] = jt[w][t][0] - jt[w][p][0];
            rel[w][t][1] = jt[w][t][1] - jt[w][p][1];
            rel[w][t][2] = jt[w][t][2] - jt[w][p][2];
        }
    }
    __syncwarp();
    if (t < 12) {
        int i = t >> 2, j = t & 3;
        ch[w][0][t] = (j < 3) ? Rm[w][0][i * 3 + j] : rel[w][0][i];
    }
    __syncwarp();
    for (int k = 1; k < KJ; k++) {
        int p = parents[k];
        if (t < 12) {
            int i = t >> 2, j = t & 3;
            float v;
            if (j < 3) {
                v = ch[w][p][i * 4 + 0] * Rm[w][k][0 * 3 + j]
                  + ch[w][p][i * 4 + 1] * Rm[w][k][1 * 3 + j]
                  + ch[w][p][i * 4 + 2] * Rm[w][k][2 * 3 + j];
            } else {
                v = ch[w][p][i * 4 + 0] * rel[w][k][0]
                  + ch[w][p][i * 4 + 1] * rel[w][k][1]
                  + ch[w][p][i * 4 + 2] * rel[w][k][2]
                  + ch[w][p][i * 4 + 3];
            }
            ch[w][k][t] = v;
        }
        __syncwarp();
    }
    if (t < KJ) {
        out[OUT_J + (size_t)b * 72 + t * 3 + 0] = ch[w][t][3];
        out[OUT_J + (size_t)b * 72 + t * 3 + 1] = ch[w][t][7];
        out[OUT_J + (size_t)b * 72 + t * 3 + 2] = ch[w][t][11];
        float* Ao = g_A + ((size_t)b * KJ + t) * 12;
#pragma unroll
        for (int i = 0; i < 3; i++) {
            float tr = ch[w][t][i * 4 + 3]
                     - (ch[w][t][i * 4 + 0] * jt[w][t][0]
                      + ch[w][t][i * 4 + 1] * jt[w][t][1]
                      + ch[w][t][i * 4 + 2] * jt[w][t][2]);
            Ao[i * 4 + 0] = ch[w][t][i * 4 + 0];
            Ao[i * 4 + 1] = ch[w][t][i * 4 + 1];
            Ao[i * 4 + 2] = ch[w][t][i * 4 + 2];
            Ao[i * 4 + 3] = tr;
        }
    }
}

// ============================================================================
// Kernel 3: R3's tf32 GEMM + FFMA2 LBS, with a 4-stage cp.async ring and
// ONE barrier per chunk (trailing barrier removed; slot written at iter kc
// was read at kc-2, separated by iter kc-1's barrier).
// Block: 192 coords x 64 batches, 256 threads (8 warps, 4m x 2n).
// ============================================================================
#define SF_STAGE 4352                 // A 16x200=3200 + B 16x72=1152
#define CS_STRIDE 65                  // Csm 192x65 = 12480 (aliases stages)
#define S_W     17408                 // 4*SF_STAGE; 24*64 = 1536
#define S_AMAT  (S_W + 1536)          // 64*288 = 18432
#define S_SD    (S_AMAT + 18432)      // 64*30 = 1920
#define S_VT    (S_SD + 1920)         // 192
#define S_BET   (S_VT + 192)          // 640
#define SMEM_FL (S_BET + 640)         // 40128
#define SMEM_BYTES (SMEM_FL * 4)      // 160512

__device__ __forceinline__ void k3_load_stage(uint32_t smb,
                                              const float* __restrict__ posedirs,
                                              int n0, int kc, int st, int tid)
{
    // A tile: rows p = kc*16 .. +15, cols n0 .. n0+191, 8B ops
#pragma unroll
    for (int j = 0; j < 6; j++) {
        int i = tid + j * 256;            // < 1536
        int row = i / 96, c2 = i % 96;
        int p = kc * 16 + row;
        int col = n0 + c2 * 2;
        int sb = 0;
        if (p < NPOSE) {
            int rem = NC - col;
            sb = (rem >= 2) ? 8 : 0;
        }
        const float* src = posedirs + (size_t)min(p, NPOSE - 1) * NC
                                    + (sb ? col : 0);
        cpa8(smb + (uint32_t)(st * SF_STAGE + row * 200 + c2 * 2) * 4, src, sb);
    }
    // B tile: pfT rows, 16B ops (always in-bounds; row 207 is zero pad)
    {
        int row = tid / 16, c4 = tid % 16;
        int p = kc * 16 + row;
        int bBase = blockIdx.x * 64;
        cpa16(smb + (uint32_t)(st * SF_STAGE + 3200 + row * 72 + c4 * 4) * 4,
              g_pfT + (size_t)p * BATCH + bBase + c4 * 4, 16);
    }
}

__global__ __launch_bounds__(256, 1) void k3_lbs(
    const float* __restrict__ posedirs,
    const float* __restrict__ lbs_w,
    const float* __restrict__ shapedirs,
    const float* __restrict__ v_template,
    const float* __restrict__ betas,
    float* __restrict__ out)
{
    extern __shared__ float sm[];
    uint32_t smb = (uint32_t)__cvta_generic_to_shared(sm);
    int tid = threadIdx.x;
    int lane = tid & 31, warp = tid >> 5;
    int bBase = blockIdx.x * 64;
    int n0 = blockIdx.y * 192;
    int v0 = n0 / 3;
    int mW = (warp & 3) * 48;
    int nW = (warp >> 2) * 32;

    // ---- epilogue tables via cp.async (group 0) ----
    {
#pragma unroll
        for (int j = 0; j < 18; j++) {
            int i = tid + j * 256;
            cpa16(smb + (uint32_t)(S_AMAT + i * 4) * 4,
                  g_A + (size_t)bBase * 288 + i * 4, 16);
        }
        int validf = (NV - v0) * 30; if (validf > 1920) validf = 1920;
#pragma unroll
        for (int j = 0; j < 2; j++) {
            int i = tid + j * 256;
            if (i < 480) {
                int fo = i * 4;
                int rem = validf - fo;
                int sb = rem >= 4 ? 16 : (rem > 0 ? rem * 4 : 0);
                cpa16(smb + (uint32_t)(S_SD + fo) * 4,
                      shapedirs + (size_t)v0 * 30 + (sb ? fo : 0), sb);
            }
        }
        if (tid < 48) {
            int fo = tid * 4;
            int validv = (NV - v0) * 3; if (validv > 192) validv = 192;
            int rem = validv - fo;
            int sb = rem >= 4 ? 16 : (rem > 0 ? rem * 4 : 0);
            cpa16(smb + (uint32_t)(S_VT + fo) * 4,
                  v_template + (size_t)v0 * 3 + (sb ? fo : 0), sb);
        }
        if (tid < 160) {
            cpa16(smb + (uint32_t)(S_BET + tid * 4) * 4,
                  betas + (size_t)bBase * 10 + tid * 4, 16);
        }
    }
    cpcommit();

    // ---- prefetch GEMM chunks 0, 1 ----
    k3_load_stage(smb, posedirs, n0, 0, 0, tid); cpcommit();
    k3_load_stage(smb, posedirs, n0, 1, 1, tid); cpcommit();

    // ---- weights (transposed [k][64]) via plain loads, overlap with cp.async
#pragma unroll
    for (int j = 0; j < 6; j++) {
        int i = tid + j * 256;
        int k = i >> 6, vl = i & 63;
        int vg = v0 + vl;
        sm[S_W + k * 64 + vl] = (vg < NV) ? lbs_w[vg * KJ + k] : 0.f;
    }

    float acc[3][4][4];
#pragma unroll
    for (int it = 0; it < 3; it++)
#pragma unroll
        for (int jt = 0; jt < 4; jt++)
#pragma unroll
            for (int e = 0; e < 4; e++) acc[it][jt][e] = 0.f;

    // ---- main k-loop: 4-stage ring, ONE barrier per chunk ----
    for (int kc = 0; kc < NCHUNKS; kc++) {
        if (kc + 2 < NCHUNKS)
            k3_load_stage(smb, posedirs, n0, kc + 2, (kc + 2) & 3, tid);
        cpcommit();
        asm volatile("cp.async.wait_group 2;");
        __syncthreads();

        const float* As = sm + (kc & 3) * SF_STAGE;
        const float* Bs = As + 3200;
#pragma unroll
        for (int kk = 0; kk < 2; kk++) {
            int k0 = kk * 8;
            uint32_t a[3][4], b[4][2];
            int ar0 = (k0 + (lane & 3)) * 200 + mW + (lane >> 2);
            int ar1 = ar0 + 4 * 200;
#pragma unroll
            for (int it = 0; it < 3; it++) {
                a[it][0] = __float_as_uint(As[ar0 + it * 16]);
                a[it][1] = __float_as_uint(As[ar0 + it * 16 + 8]);
                a[it][2] = __float_as_uint(As[ar1 + it * 16]);
                a[it][3] = __float_as_uint(As[ar1 + it * 16 + 8]);
            }
            int br0 = (k0 + (lane & 3)) * 72 + nW + (lane >> 2);
            int br1 = br0 + 4 * 72;
#pragma unroll
            for (int jt = 0; jt < 4; jt++) {
                b[jt][0] = __float_as_uint(Bs[br0 + jt * 8]);
                b[jt][1] = __float_as_uint(Bs[br1 + jt * 8]);
            }
#pragma unroll
            for (int it = 0; it < 3; it++)
#pragma unroll
                for (int jt = 0; jt < 4; jt++)
                    MMA_TF32(acc[it][jt], a[it], b[jt]);
        }
    }
    __syncthreads();   // all stage reads done before Csm overwrites stages

    // ---- dump accumulators to Csm (stage region is dead) ----
    {
        float* Cs = sm;
#pragma unroll
        for (int it = 0; it < 3; it++)
#pragma unroll
            for (int jt = 0; jt < 4; jt++) {
                int m = mW + it * 16 + (lane >> 2);
                int n = nW + jt * 8 + 2 * (lane & 3);
                Cs[m * CS_STRIDE + n]           = acc[it][jt][0];
                Cs[m * CS_STRIDE + n + 1]       = acc[it][jt][1];
                Cs[(m + 8) * CS_STRIDE + n]     = acc[it][jt][2];
                Cs[(m + 8) * CS_STRIDE + n + 1] = acc[it][jt][3];
            }
    }
    asm volatile("cp.async.wait_group 0;");   // epilogue tables ready
    __syncthreads();

    // ---- epilogue: v_posed = Csm + template + shape (fp32), then LBS ----
    int tn = tid & 15;
    int tb = tid >> 4;
    const float* Cs   = sm;
    const float* w_s  = sm + S_W;
    const float* a_s  = sm + S_AMAT;
    const float* sd_s = sm + S_SD;
    const float* vt_s = sm + S_VT;
    const float* bt_s = sm + S_BET;

    float vpf[4][12];
    {
        float bet[4][10];
#pragma unroll
        for (int bi = 0; bi < 4; bi++)
#pragma unroll
            for (int l = 0; l < NBETA; l++)
                bet[bi][l] = bt_s[(tb * 4 + bi) * 10 + l];
#pragma unroll
        for (int vi = 0; vi < 4; vi++) {
            int vl = tn * 4 + vi;
#pragma unroll
            for (int c = 0; c < 3; c++) {
                float base = vt_s[vl * 3 + c];
                float sdv[10];
#pragma unroll
                for (int l = 0; l < NBETA; l++) sdv[l] = sd_s[vl * 30 + c * 10 + l];
                int mrow = vl * 3 + c;
#pragma unroll
                for (int bi = 0; bi < 4; bi++) {
                    float s = base;
#pragma unroll
                    for (int l = 0; l < NBETA; l++) s = fmaf(bet[bi][l], sdv[l], s);
                    vpf[bi][vi * 3 + c] = Cs[mrow * CS_STRIDE + tb * 4 + bi] + s;
                }
            }
        }
    }

    // pack vertex pairs for FFMA2 LBS
    u64 xs2[4][2], ys2[4][2], zs2[4][2];
#pragma unroll
    for (int bi = 0; bi < 4; bi++)
#pragma unroll
        for (int h = 0; h < 2; h++) {
            xs2[bi][h] = pk2(vpf[bi][(2 * h) * 3 + 0], vpf[bi][(2 * h + 1) * 3 + 0]);
            ys2[bi][h] = pk2(vpf[bi][(2 * h) * 3 + 1], vpf[bi][(2 * h + 1) * 3 + 1]);
            zs2[bi][h] = pk2(vpf[bi][(2 * h) * 3 + 2], vpf[bi][(2 * h + 1) * 3 + 2]);
        }

    u64 o2[4][3][2];
#pragma unroll
    for (int bi = 0; bi < 4; bi++)
#pragma unroll
        for (int c = 0; c < 3; c++) { o2[bi][c][0] = 0ULL; o2[bi][c][1] = 0ULL; }

    for (int k = 0; k < KJ; k++) {
        float4 w4 = *(const float4*)&w_s[k * 64 + tn * 4];
        u64 w2[2] = {pk2(w4.x, w4.y), pk2(w4.z, w4.w)};
#pragma unroll
        for (int bi = 0; bi < 4; bi++) {
            const float* Ab = a_s + (tb * 4 + bi) * 288 + k * 12;
            float4 r0 = *(const float4*)&Ab[0];
            float4 r1 = *(const float4*)&Ab[4];
            float4 r2 = *(const float4*)&Ab[8];
            u64 r0x = pk2(r0.x, r0.x), r0y = pk2(r0.y, r0.y),
                r0z = pk2(r0.z, r0.z), r0w = pk2(r0.w, r0.w);
            u64 r1x = pk2(r1.x, r1.x), r1y = pk2(r1.y, r1.y),
                r1z = pk2(r1.z, r1.z), r1w = pk2(r1.w, r1.w);
            u64 r2x = pk2(r2.x, r2.x), r2y = pk2(r2.y, r2.y),
                r2z = pk2(r2.z, r2.z), r2w = pk2(r2.w, r2.w);
#pragma unroll
            for (int h = 0; h < 2; h++) {
                u64 tx = ff2(r0x, xs2[bi][h], ff2(r0y, ys2[bi][h], ff2(r0z, zs2[bi][h], r0w)));
                u64 ty = ff2(r1x, xs2[bi][h], ff2(r1y, ys2[bi][h], ff2(r1z, zs2[bi][h], r1w)));
                u64 tz = ff2(r2x, xs2[bi][h], ff2(r2y, ys2[bi][h], ff2(r2z, zs2[bi][h], r2w)));
                o2[bi][0][h] = ff2(w2[h], tx, o2[bi][0][h]);
                o2[bi][1][h] = ff2(w2[h], ty, o2[bi][1][h]);
                o2[bi][2][h] = ff2(w2[h], tz, o2[bi][2][h]);
            }
        }
    }

    // ---- store vertices (float2: NC even -> always aligned) ----
#pragma unroll
    for (int bi = 0; bi < 4; bi++) {
        float ov[12];
#pragma unroll
        for (int c = 0; c < 3; c++)
#pragma unroll
            for (int h = 0; h < 2; h++)
                upk2(o2[bi][c][h], ov[(2 * h) * 3 + c], ov[(2 * h + 1) * 3 + c]);
        int gb = bBase + tb * 4 + bi;
        size_t base = (size_t)gb * NC + n0 + tn * 12;
        int n = n0 + tn * 12;
        if (n + 12 <= NC) {
#pragma unroll
            for (int j = 0; j < 6; j++)
                *(float2*)&out[base + 2 * j] = make_float2(ov[2 * j], ov[2 * j + 1]);
        } else {
#pragma unroll
            for (int cj = 0; cj < 12; cj++)
                if (n + cj < NC) out[base + cj] = ov[cj];
        }
    }
}

// ============================================================================
extern "C" void kernel_launch(void* const* d_in, const int* in_sizes, int n_in,
                              void* d_out, int out_size)
{
    const float* body_pose     = (const float*)d_in[0];
    const float* betas         = (const float*)d_in[1];
    const float* global_orient = (const float*)d_in[2];
    const float* v_template    = (const float*)d_in[3];
    const float* shapedirs     = (const float*)d_in[4];
    const float* posedirs      = (const float*)d_in[5];
    const float* J_regressor   = (const float*)d_in[6];
    const float* lbs_weights   = (const float*)d_in[7];
    const int*   parents       = (const int*)d_in[8];
    float* out = (float*)d_out;

    static bool s_attr = false;
    if (!s_attr) {
        cudaFuncSetAttribute(k3_lbs, cudaFuncAttributeMaxDynamicSharedMemorySize,
                             SMEM_BYTES);
        s_attr = true;
    }

    k1a_jreduce<<<dim3(KJ, NSEG), 256>>>(J_regressor, v_template, shapedirs);
    k2_batch<<<BATCH / 8, 256>>>(body_pose, betas, global_orient, parents, out);
    k3_lbs<<<dim3(16, 108), 256, SMEM_BYTES>>>(posedirs, lbs_weights, shapedirs,
                                               v_template, betas, out);
}